// round 5
// baseline (speedup 1.0000x reference)
#include <cuda_runtime.h>
#include <cuda_bf16.h>
#include <cstdint>

// Problem constants
#define E_TOTAL   640000
#define N_NODES   20000
#define D_FEAT    64
#define IN_DIM    256
#define LATENT    128
#define OUT_DIM   64
#define TILE_M    128          // edges per CTA
#define NTHREADS  256

// Smem strides (floats), padded for conflict-free mma fragment loads
#define LDX  68    // X segment tile [128][64]
#define LDW  132   // W1 slab [64][128]
#define LDH  132   // H tile  [128][128]
#define LDW2 68    // W2      [128][64]

// Smem layout offsets (in floats)
//  region0 (aliased): phase1 = sX(128*68=8704) + sW(64*132=8448) = 17152
//                     phase2 = sH(128*132=16896)
#define OFF_SX    0
#define OFF_SW    8704
#define OFF_SH    0
#define OFF_SW2   17152
#define OFF_IDX   (17152 + 8704)          // 25856: sS[128], sR[128], sG[128]
#define OFF_MASK  (OFF_IDX + 384)         // 26240
#define OFF_B1    (OFF_MASK + 128)        // 26368
#define OFF_B2    (OFF_B1 + 128)          // 26496
#define SMEM_FLOATS (OFF_B2 + 64)         // 26560
#define SMEM_BYTES  (SMEM_FLOATS * 4)     // 106240

// Scratch: masked nodes, pre-converted to tf32 bit patterns
__device__ float g_mn[N_NODES * D_FEAT];
// Index dtype flag: 1 if edge_index/eg_index buffers are int64, 0 if int32
__device__ int g_is64;

__device__ __forceinline__ float to_tf32(float x) {
    uint32_t u;
    asm("cvt.rna.tf32.f32 %0, %1;" : "=r"(u) : "f"(x));
    return __uint_as_float(u);
}

__device__ __forceinline__ void mma_tf32(float c[4], const uint32_t a[4], const uint32_t b[2]) {
    asm volatile(
        "mma.sync.aligned.m16n8k8.row.col.f32.tf32.tf32.f32 "
        "{%0,%1,%2,%3}, {%4,%5,%6,%7}, {%8,%9}, {%0,%1,%2,%3};"
        : "+f"(c[0]), "+f"(c[1]), "+f"(c[2]), "+f"(c[3])
        : "r"(a[0]), "r"(a[1]), "r"(a[2]), "r"(a[3]), "r"(b[0]), "r"(b[1]));
}

__device__ __forceinline__ uint32_t fasu(float x) { return __float_as_uint(x); }

// --- detect: are index buffers int64 or int32? ---------------------------
// View edge_index as int32 words. If the true dtype is int64 (all values in
// [0, 20000)), every odd word is the zero high-half. If it is int32, odd
// words are random indices in [0, 20000): the chance all 256 samples are
// zero is (1/20000)^256 ~ 0.
__global__ void detect_kernel(const int* __restrict__ ei_words) {
    __shared__ int nz;
    if (threadIdx.x == 0) nz = 0;
    __syncthreads();
    int w = ei_words[2 * threadIdx.x * 2500 + 1];   // odd words, spread over buffer
    if (w != 0) atomicAdd(&nz, 1);
    __syncthreads();
    if (threadIdx.x == 0) g_is64 = (nz == 0) ? 1 : 0;
}

// --- prep: masked_nodes = tf32(node_attr * node_mask) -------------------
__global__ void prep_kernel(const float* __restrict__ node_attr,
                            const float* __restrict__ node_mask) {
    int i = blockIdx.x * blockDim.x + threadIdx.x;
    if (i < N_NODES * D_FEAT) {
        g_mn[i] = to_tf32(node_attr[i] * node_mask[i >> 6]);
    }
}

// --- fused edge MLP ------------------------------------------------------
__global__ __launch_bounds__(NTHREADS, 2)
void edge_mlp_kernel(const float* __restrict__ edge_attr,
                     const float* __restrict__ global_attr,
                     const float* __restrict__ edge_mask,
                     const void* __restrict__ edge_index,
                     const void* __restrict__ eg_index,
                     const float* __restrict__ W1,
                     const float* __restrict__ b1,
                     const float* __restrict__ W2,
                     const float* __restrict__ b2,
                     float* __restrict__ out) {
    extern __shared__ float sm[];
    float* sX   = sm + OFF_SX;
    float* sW   = sm + OFF_SW;
    float* sH   = sm + OFF_SH;
    float* sW2  = sm + OFF_SW2;
    int*   sS   = (int*)(sm + OFF_IDX);
    int*   sR   = sS + 128;
    int*   sG   = sR + 128;
    float* sMsk = sm + OFF_MASK;
    float* sB1  = sm + OFF_B1;
    float* sB2  = sm + OFF_B2;

    const int tid  = threadIdx.x;
    const int e0   = blockIdx.x * TILE_M;
    const int lane = tid & 31;
    const int w    = tid >> 5;
    const int g    = lane >> 2;
    const int t    = lane & 3;

    // Preload per-tile indices (dtype-agnostic), mask, biases
    if (tid < 128) {
        if (g_is64) {
            const long long* ei = (const long long*)edge_index;
            const long long* eg = (const long long*)eg_index;
            sS[tid] = (int)ei[e0 + tid];
            sR[tid] = (int)ei[E_TOTAL + e0 + tid];
            sG[tid] = (int)eg[e0 + tid];
        } else {
            const int* ei = (const int*)edge_index;
            const int* eg = (const int*)eg_index;
            sS[tid] = ei[e0 + tid];
            sR[tid] = ei[E_TOTAL + e0 + tid];
            sG[tid] = eg[e0 + tid];
        }
        sMsk[tid] = edge_mask[e0 + tid];
        sB1[tid]  = b1[tid];
        if (tid < 64) sB2[tid] = b2[tid];
    }

    // Load W2 [128][64] -> tf32 in smem (2 threads/row, 8 float4 each)
    {
        int r = tid >> 1, q = tid & 1;
        const float4* src = (const float4*)(W2 + (size_t)r * 64 + q * 32);
        float* dst = sW2 + r * LDW2 + q * 32;
        #pragma unroll
        for (int i = 0; i < 8; i++) {
            float4 v = src[i];
            v.x = to_tf32(v.x); v.y = to_tf32(v.y);
            v.z = to_tf32(v.z); v.w = to_tf32(v.w);
            *(float4*)(dst + i * 4) = v;
        }
    }

    // ---------------- GEMM1: H[128][128] = X[128][256] @ W1 -------------
    // 8 warps as 4(m) x 2(n); warp tile 32 x 64
    const int m0 = (w & 3) * 32;
    const int n0 = (w >> 2) * 64;
    float acc[2][8][4];
    #pragma unroll
    for (int mi = 0; mi < 2; mi++)
        #pragma unroll
        for (int ni = 0; ni < 8; ni++)
            #pragma unroll
            for (int j = 0; j < 4; j++) acc[mi][ni][j] = 0.0f;

    #pragma unroll 1
    for (int seg = 0; seg < 4; seg++) {
        __syncthreads();   // previous segment's reads done (also covers preload)

        // Gather X segment [128 rows][64 cols]: 2 threads/row, 8 float4 each
        {
            int r = tid >> 1, half = tid & 1;
            const float* src;
            bool needCvt;
            if (seg == 0)      { src = edge_attr   + (size_t)(e0 + r) * 64 + half * 32; needCvt = true;  }
            else if (seg == 1) { src = g_mn        + (size_t)sS[r]    * 64 + half * 32; needCvt = false; }
            else if (seg == 2) { src = g_mn        + (size_t)sR[r]    * 64 + half * 32; needCvt = false; }
            else               { src = global_attr + (size_t)sG[r]    * 64 + half * 32; needCvt = true;  }
            float* dst = sX + r * LDX + half * 32;
            #pragma unroll
            for (int i = 0; i < 8; i++) {
                float4 v = ((const float4*)src)[i];
                if (needCvt) {
                    v.x = to_tf32(v.x); v.y = to_tf32(v.y);
                    v.z = to_tf32(v.z); v.w = to_tf32(v.w);
                }
                *(float4*)(dst + i * 4) = v;
            }
        }
        // Load W1 slab [64 k][128 n]: 4 threads/row, 8 float4 each
        {
            int kr = tid >> 2, q = tid & 3;
            const float4* src = (const float4*)(W1 + (size_t)(seg * 64 + kr) * 128 + q * 32);
            float* dst = sW + kr * LDW + q * 32;
            #pragma unroll
            for (int i = 0; i < 8; i++) {
                float4 v = src[i];
                v.x = to_tf32(v.x); v.y = to_tf32(v.y);
                v.z = to_tf32(v.z); v.w = to_tf32(v.w);
                *(float4*)(dst + i * 4) = v;
            }
        }
        __syncthreads();

        // Compute: 8 k-steps of 8
        #pragma unroll
        for (int k8 = 0; k8 < 8; k8++) {
            const int kk = k8 * 8;
            uint32_t a[2][4];
            #pragma unroll
            for (int mi = 0; mi < 2; mi++) {
                const float* A = sX + (m0 + mi * 16 + g) * LDX + kk + t;
                a[mi][0] = fasu(A[0]);
                a[mi][1] = fasu(A[8 * LDX]);
                a[mi][2] = fasu(A[4]);
                a[mi][3] = fasu(A[8 * LDX + 4]);
            }
            #pragma unroll
            for (int ni = 0; ni < 8; ni++) {
                const float* B = sW + (kk + t) * LDW + n0 + ni * 8 + g;
                uint32_t b[2] = { fasu(B[0]), fasu(B[4 * LDW]) };
                mma_tf32(acc[0][ni], a[0], b);
                mma_tf32(acc[1][ni], a[1], b);
            }
        }
    }
    __syncthreads();   // all smem reads for GEMM1 complete before sH overwrite

    // Epilogue 1: bias + ReLU + cvt, store H to smem
    #pragma unroll
    for (int mi = 0; mi < 2; mi++) {
        #pragma unroll
        for (int ni = 0; ni < 8; ni++) {
            int row0 = m0 + mi * 16 + g;
            int row1 = row0 + 8;
            int col  = n0 + ni * 8 + 2 * t;
            float bb0 = sB1[col], bb1 = sB1[col + 1];
            float h00 = fmaxf(acc[mi][ni][0] + bb0, 0.0f);
            float h01 = fmaxf(acc[mi][ni][1] + bb1, 0.0f);
            float h10 = fmaxf(acc[mi][ni][2] + bb0, 0.0f);
            float h11 = fmaxf(acc[mi][ni][3] + bb1, 0.0f);
            *(float2*)(sH + row0 * LDH + col) = make_float2(to_tf32(h00), to_tf32(h01));
            *(float2*)(sH + row1 * LDH + col) = make_float2(to_tf32(h10), to_tf32(h11));
        }
    }
    __syncthreads();

    // ---------------- GEMM2: OUT[128][64] = H[128][128] @ W2 ------------
    // 8 warps as 4(m) x 2(n); warp tile 32 x 32
    const int m2 = (w & 3) * 32;
    const int n2 = (w >> 2) * 32;
    float acc2[2][4][4];
    #pragma unroll
    for (int mi = 0; mi < 2; mi++)
        #pragma unroll
        for (int ni = 0; ni < 4; ni++)
            #pragma unroll
            for (int j = 0; j < 4; j++) acc2[mi][ni][j] = 0.0f;

    #pragma unroll
    for (int k8 = 0; k8 < 16; k8++) {
        const int kk = k8 * 8;
        uint32_t a[2][4];
        #pragma unroll
        for (int mi = 0; mi < 2; mi++) {
            const float* A = sH + (m2 + mi * 16 + g) * LDH + kk + t;
            a[mi][0] = fasu(A[0]);
            a[mi][1] = fasu(A[8 * LDH]);
            a[mi][2] = fasu(A[4]);
            a[mi][3] = fasu(A[8 * LDH + 4]);
        }
        #pragma unroll
        for (int ni = 0; ni < 4; ni++) {
            const float* B = sW2 + (kk + t) * LDW2 + n2 + ni * 8 + g;
            uint32_t b[2] = { fasu(B[0]), fasu(B[4 * LDW2]) };
            mma_tf32(acc2[0][ni], a[0], b);
            mma_tf32(acc2[1][ni], a[1], b);
        }
    }

    // Epilogue 2: mask * (acc + b2), direct global store (float2)
    #pragma unroll
    for (int mi = 0; mi < 2; mi++) {
        int row0 = m2 + mi * 16 + g;
        int row1 = row0 + 8;
        float mk0 = sMsk[row0];
        float mk1 = sMsk[row1];
        #pragma unroll
        for (int ni = 0; ni < 4; ni++) {
            int col = n2 + ni * 8 + 2 * t;
            float bb0 = sB2[col], bb1 = sB2[col + 1];
            float2 v0 = make_float2(mk0 * (acc2[mi][ni][0] + bb0),
                                    mk0 * (acc2[mi][ni][1] + bb1));
            float2 v1 = make_float2(mk1 * (acc2[mi][ni][2] + bb0),
                                    mk1 * (acc2[mi][ni][3] + bb1));
            *(float2*)(out + (size_t)(e0 + row0) * 64 + col) = v0;
            *(float2*)(out + (size_t)(e0 + row1) * 64 + col) = v1;
        }
    }
}

extern "C" void kernel_launch(void* const* d_in, const int* in_sizes, int n_in,
                              void* d_out, int out_size) {
    const float* node_attr   = (const float*)d_in[0];
    const float* edge_attr   = (const float*)d_in[1];
    const float* global_attr = (const float*)d_in[2];
    const float* node_mask   = (const float*)d_in[3];
    const float* edge_mask   = (const float*)d_in[4];
    const void*  edge_index  = d_in[5];
    const void*  eg_index    = d_in[6];
    const float* W1          = (const float*)d_in[7];
    const float* b1          = (const float*)d_in[8];
    const float* W2          = (const float*)d_in[9];
    const float* b2          = (const float*)d_in[10];
    float*       out         = (float*)d_out;

    cudaFuncSetAttribute(edge_mlp_kernel,
                         cudaFuncAttributeMaxDynamicSharedMemorySize, SMEM_BYTES);

    detect_kernel<<<1, 256>>>((const int*)edge_index);
    prep_kernel<<<(N_NODES * D_FEAT + 255) / 256, 256>>>(node_attr, node_mask);
    edge_mlp_kernel<<<E_TOTAL / TILE_M, NTHREADS, SMEM_BYTES>>>(
        edge_attr, global_attr, edge_mask, edge_index, eg_index,
        W1, b1, W2, b2, out);
}

// round 10
// speedup vs baseline: 3.0763x; 3.0763x over previous
#include <cuda_runtime.h>
#include <cuda_fp16.h>
#include <cstdint>

// Problem constants
#define E_TOTAL   640000
#define N_NODES   20000
#define TILE_M    128
#define NTHREADS  512

// half2 strides (in half2 units)
#define LDA  36   // X seg [128][32 h2] and W1 seg [128][32 h2], padded
#define LDH  68   // H [128][64 h2] and W2T [64][64 h2], padded

// smem byte offsets
#define SMEM_X    0        // 128*36*4 = 18432
#define SMEM_W1   18432    // 18432  -> 36864
#define SMEM_H    0        // 128*68*4 = 34816 (aliases X+W1)
#define SMEM_W2T  36864    // 64*68*4 = 17408 -> 54272
#define OFF_S     54272
#define OFF_R     54784
#define OFF_G     55296
#define OFF_MSK   55808
#define OFF_B1    56320
#define OFF_B2    56832
#define SMEM_BYTES 57088

// ---------- scratch (fp16 pre-converted) ----------
__device__ __half2 g_mn2[N_NODES * 32];    // masked nodes, [node][32 h2]
__device__ __half2 g_w1t2[128 * 128];      // W1^T [n=128][k2=128]
__device__ __half2 g_w2t2[64 * 64];        // W2^T [n=64][k2=64]
__device__ int     g_is64;

__device__ __forceinline__ void mma_f16(float c[4], const uint32_t a[4], const uint32_t b[2]) {
    asm volatile(
        "mma.sync.aligned.m16n8k16.row.col.f32.f16.f16.f32 "
        "{%0,%1,%2,%3}, {%4,%5,%6,%7}, {%8,%9}, {%0,%1,%2,%3};"
        : "+f"(c[0]), "+f"(c[1]), "+f"(c[2]), "+f"(c[3])
        : "r"(a[0]), "r"(a[1]), "r"(a[2]), "r"(a[3]), "r"(b[0]), "r"(b[1]));
}
__device__ __forceinline__ uint32_t h2u(__half2 h) { return *(uint32_t*)&h; }

// ---------- detect int64 vs int32 indices ----------
__global__ void detect_kernel(const int* __restrict__ ei_words) {
    __shared__ int nz;
    if (threadIdx.x == 0) nz = 0;
    __syncthreads();
    int w = ei_words[2 * threadIdx.x * 2500 + 1];
    if (w != 0) atomicAdd(&nz, 1);
    __syncthreads();
    if (threadIdx.x == 0) g_is64 = (nz == 0) ? 1 : 0;
}

// ---------- prep kernels ----------
__global__ void prep_mn(const float* __restrict__ na, const float* __restrict__ nm) {
    int i = blockIdx.x * blockDim.x + threadIdx.x;
    if (i < N_NODES * 32) {
        int node = i >> 5, c2 = i & 31;
        float m = nm[node];
        const float* s = na + (size_t)node * 64 + c2 * 2;
        g_mn2[i] = __floats2half2_rn(s[0] * m, s[1] * m);
    }
}
__global__ void prep_w1t(const float* __restrict__ W1) {   // W1 [256][128]
    int i = blockIdx.x * blockDim.x + threadIdx.x;
    if (i < 128 * 128) {
        int n = i >> 7, k2 = i & 127;
        g_w1t2[i] = __floats2half2_rn(W1[(2 * k2) * 128 + n], W1[(2 * k2 + 1) * 128 + n]);
    }
}
__global__ void prep_w2t(const float* __restrict__ W2) {   // W2 [128][64]
    int i = blockIdx.x * blockDim.x + threadIdx.x;
    if (i < 64 * 64) {
        int n = i >> 6, k2 = i & 63;
        g_w2t2[i] = __floats2half2_rn(W2[(2 * k2) * 64 + n], W2[(2 * k2 + 1) * 64 + n]);
    }
}

// ---------- fused edge MLP (fp16 mma.sync) ----------
__global__ __launch_bounds__(NTHREADS, 2)
void edge_mlp_kernel(const float* __restrict__ edge_attr,
                     const float* __restrict__ global_attr,
                     const float* __restrict__ edge_mask,
                     const void* __restrict__ edge_index,
                     const void* __restrict__ eg_index,
                     const float* __restrict__ b1,
                     const float* __restrict__ b2,
                     float* __restrict__ out) {
    extern __shared__ char smp[];
    __half2* sX2  = (__half2*)(smp + SMEM_X);
    __half2* sW12 = (__half2*)(smp + SMEM_W1);
    __half2* sH2  = (__half2*)(smp + SMEM_H);
    __half2* sW22 = (__half2*)(smp + SMEM_W2T);
    int*   sS   = (int*)(smp + OFF_S);
    int*   sR   = (int*)(smp + OFF_R);
    int*   sG   = (int*)(smp + OFF_G);
    float* sMsk = (float*)(smp + OFF_MSK);
    float* sB1  = (float*)(smp + OFF_B1);
    float* sB2  = (float*)(smp + OFF_B2);

    const int tid  = threadIdx.x;
    const int lane = tid & 31;
    const int w    = tid >> 5;           // 0..15
    const int g    = lane >> 2;
    const int t    = lane & 3;
    const int e0   = blockIdx.x * TILE_M;

    // indices / mask / biases
    if (tid < 128) {
        if (g_is64) {
            const long long* ei = (const long long*)edge_index;
            const long long* eg = (const long long*)eg_index;
            sS[tid] = (int)ei[e0 + tid];
            sR[tid] = (int)ei[E_TOTAL + e0 + tid];
            sG[tid] = (int)eg[e0 + tid];
        } else {
            const int* ei = (const int*)edge_index;
            const int* eg = (const int*)eg_index;
            sS[tid] = ei[e0 + tid];
            sR[tid] = ei[E_TOTAL + e0 + tid];
            sG[tid] = eg[e0 + tid];
        }
        sMsk[tid] = edge_mask[e0 + tid];
        sB1[tid]  = b1[tid];
        if (tid < 64) sB2[tid] = b2[tid];
    }

    // W2^T [64][64 h2] -> smem (2048 uint2 chunks / 512 thr = 4 iters)
    #pragma unroll
    for (int i = 0; i < 4; i++) {
        int f = i * NTHREADS + tid, r = f >> 5, q = f & 31;
        uint2 u = *(const uint2*)(g_w2t2 + r * 64 + q * 2);
        *(uint2*)(sW22 + r * LDH + q * 2) = u;
    }

    // ---------------- GEMM1: H[128][128] = X[128][256] @ W1 -------------
    // 16 warps as 4(m) x 4(n); warp tile 32 x 32
    const int m0  = (w & 3) * 32;
    const int n0w = (w >> 2) * 32;
    float acc[2][4][4];
    #pragma unroll
    for (int mi = 0; mi < 2; mi++)
        #pragma unroll
        for (int ni = 0; ni < 4; ni++)
            #pragma unroll
            for (int j = 0; j < 4; j++) acc[mi][ni][j] = 0.0f;

    #pragma unroll 1
    for (int seg = 0; seg < 4; seg++) {
        __syncthreads();   // prev segment reads done (seg0: preload visible)

        // gather X segment [128 rows][32 h2]; 2048 uint2 chunks
        #pragma unroll
        for (int i = 0; i < 4; i++) {
            int f = i * NTHREADS + tid, r = f >> 4, q = f & 15;
            uint2 u;
            if (seg == 1 || seg == 2) {
                int node = (seg == 1) ? sS[r] : sR[r];
                u = *(const uint2*)(g_mn2 + (size_t)node * 32 + q * 2);
            } else {
                const float* src = (seg == 0)
                    ? edge_attr   + (size_t)(e0 + r) * 64 + q * 4
                    : global_attr + (size_t)sG[r]    * 64 + q * 4;
                float4 v = *(const float4*)src;
                __half2 p0 = __floats2half2_rn(v.x, v.y);
                __half2 p1 = __floats2half2_rn(v.z, v.w);
                u.x = h2u(p0); u.y = h2u(p1);
            }
            *(uint2*)(sX2 + r * LDA + q * 2) = u;
        }
        // W1^T segment [128 n][32 h2]
        #pragma unroll
        for (int i = 0; i < 4; i++) {
            int f = i * NTHREADS + tid, r = f >> 4, q = f & 15;
            uint2 u = *(const uint2*)(g_w1t2 + r * 128 + seg * 32 + q * 2);
            *(uint2*)(sW12 + r * LDA + q * 2) = u;
        }
        __syncthreads();

        // 4 k16-steps per segment
        #pragma unroll
        for (int k16 = 0; k16 < 4; k16++) {
            const int kk2 = k16 * 8;
            uint32_t a[2][4];
            #pragma unroll
            for (int mi = 0; mi < 2; mi++) {
                const uint32_t* A0 = (const uint32_t*)(sX2 + (m0 + mi * 16 + g) * LDA + kk2 + t);
                const uint32_t* A1 = (const uint32_t*)(sX2 + (m0 + mi * 16 + g + 8) * LDA + kk2 + t);
                a[mi][0] = A0[0]; a[mi][1] = A1[0];
                a[mi][2] = A0[4]; a[mi][3] = A1[4];
            }
            #pragma unroll
            for (int ni = 0; ni < 4; ni++) {
                const uint32_t* B = (const uint32_t*)(sW12 + (n0w + ni * 8 + g) * LDA + kk2 + t);
                uint32_t b[2] = { B[0], B[4] };
                mma_f16(acc[0][ni], a[0], b);
                mma_f16(acc[1][ni], a[1], b);
            }
        }
    }
    __syncthreads();   // all GEMM1 smem reads done before sH overwrite

    // ---- epilogue 1: bias + ReLU -> half2 -> sH ----
    #pragma unroll
    for (int mi = 0; mi < 2; mi++) {
        #pragma unroll
        for (int ni = 0; ni < 4; ni++) {
            int row0 = m0 + mi * 16 + g;
            int row1 = row0 + 8;
            int col  = n0w + ni * 8 + 2 * t;
            float bb0 = sB1[col], bb1 = sB1[col + 1];
            float h00 = fmaxf(acc[mi][ni][0] + bb0, 0.0f);
            float h01 = fmaxf(acc[mi][ni][1] + bb1, 0.0f);
            float h10 = fmaxf(acc[mi][ni][2] + bb0, 0.0f);
            float h11 = fmaxf(acc[mi][ni][3] + bb1, 0.0f);
            sH2[row0 * LDH + (col >> 1)] = __floats2half2_rn(h00, h01);
            sH2[row1 * LDH + (col >> 1)] = __floats2half2_rn(h10, h11);
        }
    }
    __syncthreads();

    // ---------------- GEMM2: OUT[128][64] = H[128][128] @ W2 ------------
    // 16 warps as 4(m) x 4(n); warp tile 32 x 16
    const int m2 = (w & 3) * 32;
    const int n2 = (w >> 2) * 16;
    float acc2[2][2][4];
    #pragma unroll
    for (int mi = 0; mi < 2; mi++)
        #pragma unroll
        for (int ni = 0; ni < 2; ni++)
            #pragma unroll
            for (int j = 0; j < 4; j++) acc2[mi][ni][j] = 0.0f;

    #pragma unroll
    for (int k16 = 0; k16 < 8; k16++) {
        const int kk2 = k16 * 8;
        uint32_t a[2][4];
        #pragma unroll
        for (int mi = 0; mi < 2; mi++) {
            const uint32_t* A0 = (const uint32_t*)(sH2 + (m2 + mi * 16 + g) * LDH + kk2 + t);
            const uint32_t* A1 = (const uint32_t*)(sH2 + (m2 + mi * 16 + g + 8) * LDH + kk2 + t);
            a[mi][0] = A0[0]; a[mi][1] = A1[0];
            a[mi][2] = A0[4]; a[mi][3] = A1[4];
        }
        #pragma unroll
        for (int ni = 0; ni < 2; ni++) {
            const uint32_t* B = (const uint32_t*)(sW22 + (n2 + ni * 8 + g) * LDH + kk2 + t);
            uint32_t b[2] = { B[0], B[4] };
            mma_f16(acc2[0][ni], a[0], b);
            mma_f16(acc2[1][ni], a[1], b);
        }
    }

    // ---- epilogue 2: mask * (acc + b2), direct float2 stores ----
    #pragma unroll
    for (int mi = 0; mi < 2; mi++) {
        int row0 = m2 + mi * 16 + g;
        int row1 = row0 + 8;
        float mk0 = sMsk[row0];
        float mk1 = sMsk[row1];
        #pragma unroll
        for (int ni = 0; ni < 2; ni++) {
            int col = n2 + ni * 8 + 2 * t;
            float bb0 = sB2[col], bb1 = sB2[col + 1];
            float2 v0 = make_float2(mk0 * (acc2[mi][ni][0] + bb0),
                                    mk0 * (acc2[mi][ni][1] + bb1));
            float2 v1 = make_float2(mk1 * (acc2[mi][ni][2] + bb0),
                                    mk1 * (acc2[mi][ni][3] + bb1));
            *(float2*)(out + (size_t)(e0 + row0) * 64 + col) = v0;
            *(float2*)(out + (size_t)(e0 + row1) * 64 + col) = v1;
        }
    }
}

extern "C" void kernel_launch(void* const* d_in, const int* in_sizes, int n_in,
                              void* d_out, int out_size) {
    const float* node_attr   = (const float*)d_in[0];
    const float* edge_attr   = (const float*)d_in[1];
    const float* global_attr = (const float*)d_in[2];
    const float* node_mask   = (const float*)d_in[3];
    const float* edge_mask   = (const float*)d_in[4];
    const void*  edge_index  = d_in[5];
    const void*  eg_index    = d_in[6];
    const float* W1          = (const float*)d_in[7];
    const float* b1          = (const float*)d_in[8];
    const float* W2          = (const float*)d_in[9];
    const float* b2          = (const float*)d_in[10];
    float*       out         = (float*)d_out;

    cudaFuncSetAttribute(edge_mlp_kernel,
                         cudaFuncAttributeMaxDynamicSharedMemorySize, SMEM_BYTES);

    detect_kernel<<<1, 256>>>((const int*)edge_index);
    prep_mn<<<(N_NODES * 32 + 255) / 256, 256>>>(node_attr, node_mask);
    prep_w1t<<<(128 * 128 + 255) / 256, 256>>>(W1);
    prep_w2t<<<(64 * 64 + 255) / 256, 256>>>(W2);
    edge_mlp_kernel<<<E_TOTAL / TILE_M, NTHREADS, SMEM_BYTES>>>(
        edge_attr, global_attr, edge_mask, edge_index, eg_index, b1, b2, out);
}

// round 11
// speedup vs baseline: 3.2122x; 1.0442x over previous
#include <cuda_runtime.h>
#include <cuda_fp16.h>
#include <cstdint>

// Problem constants
#define E_TOTAL   640000
#define N_NODES   20000
#define N_GRAPHS  16
#define TILE_M    128
#define NTHREADS  512

// half2 strides (in half2 units)
#define LDA  68   // X seg [128][64 h2] and W1 seg [128][64 h2], padded
#define LDH  68   // H [128][64 h2] and W2T [64][64 h2], padded

// smem byte offsets
#define SMEM_X    0        // 128*68*4 = 34816
#define SMEM_W1   34816    // -> 69632
#define SMEM_H    0        // 34816 (aliases X)
#define SMEM_W2T  69632    // 64*68*4 = 17408 -> 87040
#define OFF_S     87040
#define OFF_R     87552
#define OFF_G     88064
#define OFF_MSK   88576
#define OFF_B1    89088
#define OFF_B2    89600
#define SMEM_BYTES 89856

// ---------- scratch (fp16 pre-converted) ----------
__device__ __half2 g_mn2[N_NODES * 32];    // masked nodes [node][32 h2]
__device__ __half2 g_w1t2[128 * 128];      // W1^T [n=128][k2=128]
__device__ __half2 g_w2t2[64 * 64];        // W2^T [n=64][k2=64]
__device__ __half2 g_ga2[N_GRAPHS * 32];   // global_attr fp16 [g][32 h2]
__device__ int     g_is64;

__device__ __forceinline__ void mma_f16(float c[4], const uint32_t a[4], const uint32_t b[2]) {
    asm volatile(
        "mma.sync.aligned.m16n8k16.row.col.f32.f16.f16.f32 "
        "{%0,%1,%2,%3}, {%4,%5,%6,%7}, {%8,%9}, {%0,%1,%2,%3};"
        : "+f"(c[0]), "+f"(c[1]), "+f"(c[2]), "+f"(c[3])
        : "r"(a[0]), "r"(a[1]), "r"(a[2]), "r"(a[3]), "r"(b[0]), "r"(b[1]));
}
__device__ __forceinline__ uint32_t h2u(__half2 h) { return *(uint32_t*)&h; }

// ---------- single prep kernel (keeps launch count at 2 per call) ----------
// blocks [0,2500): masked nodes; [2500,2564): W1^T; [2564,2580): W2^T;
// [2580,2582): global_attr fp16; 2582: index dtype detect.
#define PREP_BLOCKS 2583
__global__ void prep_all(const float* __restrict__ na, const float* __restrict__ nm,
                         const float* __restrict__ W1, const float* __restrict__ W2,
                         const float* __restrict__ ga, const int* __restrict__ ei_words) {
    int bid = blockIdx.x, tid = threadIdx.x;
    if (bid < 2500) {
        int i = bid * 256 + tid;
        if (i < N_NODES * 32) {
            int node = i >> 5, c2 = i & 31;
            float m = nm[node];
            const float* s = na + (size_t)node * 64 + c2 * 2;
            g_mn2[i] = __floats2half2_rn(s[0] * m, s[1] * m);
        }
    } else if (bid < 2564) {
        int j = (bid - 2500) * 256 + tid;       // < 16384
        int n = j >> 7, k2 = j & 127;
        g_w1t2[j] = __floats2half2_rn(W1[(2 * k2) * 128 + n], W1[(2 * k2 + 1) * 128 + n]);
    } else if (bid < 2580) {
        int j = (bid - 2564) * 256 + tid;       // < 4096
        int n = j >> 6, k2 = j & 63;
        g_w2t2[j] = __floats2half2_rn(W2[(2 * k2) * 64 + n], W2[(2 * k2 + 1) * 64 + n]);
    } else if (bid < 2582) {
        int j = (bid - 2580) * 256 + tid;       // < 512
        if (j < N_GRAPHS * 32) {
            int gi = j >> 5, c2 = j & 31;
            g_ga2[j] = __floats2half2_rn(ga[gi * 64 + 2 * c2], ga[gi * 64 + 2 * c2 + 1]);
        }
    } else {
        __shared__ int nz;
        if (tid == 0) nz = 0;
        __syncthreads();
        int w = ei_words[2 * tid * 2500 + 1];
        if (w != 0) atomicAdd(&nz, 1);
        __syncthreads();
        if (tid == 0) g_is64 = (nz == 0) ? 1 : 0;
    }
}

// ---------- fused edge MLP (fp16 mma.sync, 2 K-segments) ----------
__global__ __launch_bounds__(NTHREADS, 2)
void edge_mlp_kernel(const float* __restrict__ edge_attr,
                     const float* __restrict__ edge_mask,
                     const void* __restrict__ edge_index,
                     const void* __restrict__ eg_index,
                     const float* __restrict__ b1,
                     const float* __restrict__ b2,
                     float* __restrict__ out) {
    extern __shared__ char smp[];
    __half2* sX2  = (__half2*)(smp + SMEM_X);
    __half2* sW12 = (__half2*)(smp + SMEM_W1);
    __half2* sH2  = (__half2*)(smp + SMEM_H);
    __half2* sW22 = (__half2*)(smp + SMEM_W2T);
    int*   sS   = (int*)(smp + OFF_S);
    int*   sR   = (int*)(smp + OFF_R);
    int*   sG   = (int*)(smp + OFF_G);
    float* sMsk = (float*)(smp + OFF_MSK);
    float* sB1  = (float*)(smp + OFF_B1);
    float* sB2  = (float*)(smp + OFF_B2);

    const int tid  = threadIdx.x;
    const int lane = tid & 31;
    const int w    = tid >> 5;           // 0..15
    const int g    = lane >> 2;
    const int t    = lane & 3;
    const int e0   = blockIdx.x * TILE_M;

    // indices / mask / biases
    if (tid < 128) {
        if (g_is64) {
            const long long* ei = (const long long*)edge_index;
            const long long* eg = (const long long*)eg_index;
            sS[tid] = (int)ei[e0 + tid];
            sR[tid] = (int)ei[E_TOTAL + e0 + tid];
            sG[tid] = (int)eg[e0 + tid];
        } else {
            const int* ei = (const int*)edge_index;
            const int* eg = (const int*)eg_index;
            sS[tid] = ei[e0 + tid];
            sR[tid] = ei[E_TOTAL + e0 + tid];
            sG[tid] = eg[e0 + tid];
        }
        sMsk[tid] = edge_mask[e0 + tid];
        sB1[tid]  = b1[tid];
        if (tid < 64) sB2[tid] = b2[tid];
    }

    // W2^T [64][64 h2] -> smem (2048 uint2 chunks / 512 thr = 4 iters)
    #pragma unroll
    for (int i = 0; i < 4; i++) {
        int f = i * NTHREADS + tid, r = f >> 5, q = f & 31;
        uint2 u = *(const uint2*)(g_w2t2 + r * 64 + q * 2);
        *(uint2*)(sW22 + r * LDH + q * 2) = u;
    }

    // ---------------- GEMM1: H[128][128] = X[128][256] @ W1 -------------
    // 16 warps as 4(m) x 4(n); warp tile 32 x 32
    const int m0  = (w & 3) * 32;
    const int n0w = (w >> 2) * 32;
    float acc[2][4][4];
    #pragma unroll
    for (int mi = 0; mi < 2; mi++)
        #pragma unroll
        for (int ni = 0; ni < 4; ni++)
            #pragma unroll
            for (int j = 0; j < 4; j++) acc[mi][ni][j] = 0.0f;

    #pragma unroll 1
    for (int seg = 0; seg < 2; seg++) {
        __syncthreads();   // prev segment reads done (seg0: idx preload visible)

        // X half0 (h2 cols 0..31): seg0 = edge_attr (cvt), seg1 = receivers
        #pragma unroll
        for (int i = 0; i < 4; i++) {
            int f = i * NTHREADS + tid, r = f >> 4, q = f & 15;
            uint2 u;
            if (seg == 0) {
                float4 v = *(const float4*)(edge_attr + (size_t)(e0 + r) * 64 + q * 4);
                u.x = h2u(__floats2half2_rn(v.x, v.y));
                u.y = h2u(__floats2half2_rn(v.z, v.w));
            } else {
                u = *(const uint2*)(g_mn2 + (size_t)sR[r] * 32 + q * 2);
            }
            *(uint2*)(sX2 + r * LDA + q * 2) = u;
        }
        // X half1 (h2 cols 32..63): seg0 = senders, seg1 = globals
        #pragma unroll
        for (int i = 0; i < 4; i++) {
            int f = i * NTHREADS + tid, r = f >> 4, q = f & 15;
            uint2 u;
            if (seg == 0) u = *(const uint2*)(g_mn2 + (size_t)sS[r] * 32 + q * 2);
            else          u = *(const uint2*)(g_ga2 + (size_t)sG[r] * 32 + q * 2);
            *(uint2*)(sX2 + r * LDA + 32 + q * 2) = u;
        }
        // W1^T segment [128 n][64 h2]: 4096 uint2 chunks / 512 thr = 8 iters
        #pragma unroll
        for (int i = 0; i < 8; i++) {
            int f = i * NTHREADS + tid, r = f >> 5, q = f & 31;
            uint2 u = *(const uint2*)(g_w1t2 + r * 128 + seg * 64 + q * 2);
            *(uint2*)(sW12 + r * LDA + q * 2) = u;
        }
        __syncthreads();

        // 8 k16-steps per segment
        #pragma unroll
        for (int k16 = 0; k16 < 8; k16++) {
            const int kk2 = k16 * 8;
            uint32_t a[2][4];
            #pragma unroll
            for (int mi = 0; mi < 2; mi++) {
                const uint32_t* A0 = (const uint32_t*)(sX2 + (m0 + mi * 16 + g) * LDA + kk2 + t);
                const uint32_t* A1 = (const uint32_t*)(sX2 + (m0 + mi * 16 + g + 8) * LDA + kk2 + t);
                a[mi][0] = A0[0]; a[mi][1] = A1[0];
                a[mi][2] = A0[4]; a[mi][3] = A1[4];
            }
            #pragma unroll
            for (int ni = 0; ni < 4; ni++) {
                const uint32_t* B = (const uint32_t*)(sW12 + (n0w + ni * 8 + g) * LDA + kk2 + t);
                uint32_t b[2] = { B[0], B[4] };
                mma_f16(acc[0][ni], a[0], b);
                mma_f16(acc[1][ni], a[1], b);
            }
        }
    }
    __syncthreads();   // all GEMM1 smem reads done before sH overwrite

    // ---- epilogue 1: bias + ReLU -> half2 -> sH ----
    #pragma unroll
    for (int mi = 0; mi < 2; mi++) {
        #pragma unroll
        for (int ni = 0; ni < 4; ni++) {
            int row0 = m0 + mi * 16 + g;
            int row1 = row0 + 8;
            int col  = n0w + ni * 8 + 2 * t;
            float bb0 = sB1[col], bb1 = sB1[col + 1];
            float h00 = fmaxf(acc[mi][ni][0] + bb0, 0.0f);
            float h01 = fmaxf(acc[mi][ni][1] + bb1, 0.0f);
            float h10 = fmaxf(acc[mi][ni][2] + bb0, 0.0f);
            float h11 = fmaxf(acc[mi][ni][3] + bb1, 0.0f);
            sH2[row0 * LDH + (col >> 1)] = __floats2half2_rn(h00, h01);
            sH2[row1 * LDH + (col >> 1)] = __floats2half2_rn(h10, h11);
        }
    }
    __syncthreads();

    // ---------------- GEMM2: OUT[128][64] = H[128][128] @ W2 ------------
    // 16 warps as 4(m) x 4(n); warp tile 32 x 16
    const int m2 = (w & 3) * 32;
    const int n2 = (w >> 2) * 16;
    float acc2[2][2][4];
    #pragma unroll
    for (int mi = 0; mi < 2; mi++)
        #pragma unroll
        for (int ni = 0; ni < 2; ni++)
            #pragma unroll
            for (int j = 0; j < 4; j++) acc2[mi][ni][j] = 0.0f;

    #pragma unroll
    for (int k16 = 0; k16 < 8; k16++) {
        const int kk2 = k16 * 8;
        uint32_t a[2][4];
        #pragma unroll
        for (int mi = 0; mi < 2; mi++) {
            const uint32_t* A0 = (const uint32_t*)(sH2 + (m2 + mi * 16 + g) * LDH + kk2 + t);
            const uint32_t* A1 = (const uint32_t*)(sH2 + (m2 + mi * 16 + g + 8) * LDH + kk2 + t);
            a[mi][0] = A0[0]; a[mi][1] = A1[0];
            a[mi][2] = A0[4]; a[mi][3] = A1[4];
        }
        #pragma unroll
        for (int ni = 0; ni < 2; ni++) {
            const uint32_t* B = (const uint32_t*)(sW22 + (n2 + ni * 8 + g) * LDH + kk2 + t);
            uint32_t b[2] = { B[0], B[4] };
            mma_f16(acc2[0][ni], a[0], b);
            mma_f16(acc2[1][ni], a[1], b);
        }
    }

    // ---- epilogue 2: mask * (acc + b2), direct float2 stores ----
    #pragma unroll
    for (int mi = 0; mi < 2; mi++) {
        int row0 = m2 + mi * 16 + g;
        int row1 = row0 + 8;
        float mk0 = sMsk[row0];
        float mk1 = sMsk[row1];
        #pragma unroll
        for (int ni = 0; ni < 2; ni++) {
            int col = n2 + ni * 8 + 2 * t;
            float bb0 = sB2[col], bb1 = sB2[col + 1];
            float2 v0 = make_float2(mk0 * (acc2[mi][ni][0] + bb0),
                                    mk0 * (acc2[mi][ni][1] + bb1));
            float2 v1 = make_float2(mk1 * (acc2[mi][ni][2] + bb0),
                                    mk1 * (acc2[mi][ni][3] + bb1));
            *(float2*)(out + (size_t)(e0 + row0) * 64 + col) = v0;
            *(float2*)(out + (size_t)(e0 + row1) * 64 + col) = v1;
        }
    }
}

extern "C" void kernel_launch(void* const* d_in, const int* in_sizes, int n_in,
                              void* d_out, int out_size) {
    const float* node_attr   = (const float*)d_in[0];
    const float* edge_attr   = (const float*)d_in[1];
    const float* global_attr = (const float*)d_in[2];
    const float* node_mask   = (const float*)d_in[3];
    const float* edge_mask   = (const float*)d_in[4];
    const void*  edge_index  = d_in[5];
    const void*  eg_index    = d_in[6];
    const float* W1          = (const float*)d_in[7];
    const float* b1          = (const float*)d_in[8];
    const float* W2          = (const float*)d_in[9];
    const float* b2          = (const float*)d_in[10];
    float*       out         = (float*)d_out;

    cudaFuncSetAttribute(edge_mlp_kernel,
                         cudaFuncAttributeMaxDynamicSharedMemorySize, SMEM_BYTES);

    prep_all<<<PREP_BLOCKS, 256>>>(node_attr, node_mask, W1, W2, global_attr,
                                   (const int*)edge_index);
    edge_mlp_kernel<<<E_TOTAL / TILE_M, NTHREADS, SMEM_BYTES>>>(
        edge_attr, edge_mask, edge_index, eg_index, b1, b2, out);
}